// round 9
// baseline (speedup 1.0000x reference)
#include <cuda_runtime.h>
#include <cuda_bf16.h>
#include <cstdint>

#define HWL    32768          // 32*32*32 spatial positions
#define CDIM   64             // in channels == out channels
#define KPROD  27             // 3*3*3 taps
#define P_TILE 128            // output positions per CTA (= GEMM M)

// Padded channels-last x: guard bands let the gather skip ALL bounds checks
// (validity is folded into interpolation weights; pads are zero-initialized).
// Addressing clamp range [-8,40] per dim -> idx in (-541184, 2773632).
#define PAD_LO 560000
#define PAD_HI 700000
__device__ __align__(16) float g_xTp[PAD_LO + HWL * CDIM + PAD_HI];
__device__ __align__(16) unsigned char g_wb[KPROD * 16384];
// per tap: [b0: 8KB][b1: 8KB]; rows = cout (128B each, 64 c x bf16), SW128-swizzled

__device__ __forceinline__ uint32_t s2u(const void* p) {
    uint32_t a;
    asm("{ .reg .u64 t; cvta.to.shared.u64 t, %1; cvt.u32.u64 %0, t; }"
        : "=r"(a) : "l"(p));
    return a;
}

__device__ __forceinline__ void ldmx4(uint32_t* r, uint32_t addr) {
    asm volatile("ldmatrix.sync.aligned.m8n8.x4.shared.b16 {%0,%1,%2,%3}, [%4];"
                 : "=r"(r[0]), "=r"(r[1]), "=r"(r[2]), "=r"(r[3]) : "r"(addr));
}

__device__ __forceinline__ void mma16816(float* d, const uint32_t* a,
                                         uint32_t b0, uint32_t b1) {
    asm volatile(
        "mma.sync.aligned.m16n8k16.row.col.f32.bf16.bf16.f32 "
        "{%0,%1,%2,%3}, {%4,%5,%6,%7}, {%8,%9}, {%0,%1,%2,%3};"
        : "+f"(d[0]), "+f"(d[1]), "+f"(d[2]), "+f"(d[3])
        : "r"(a[0]), "r"(a[1]), "r"(a[2]), "r"(a[3]), "r"(b0), "r"(b1));
}

// smem layout (bytes from dynamic smem base)
#define OFF_A      0
#define A_BUF_SZ   32768
#define A_LO       16384
#define OFF_W      65536
#define SMEM_BYTES (OFF_W + 32768)   // 96 KB -> 2 CTAs/SM

// ---------------------------------------------------------------------------
// Fused prep: blocks [0,2048) transpose x -> g_xTp[PAD_LO + s*64 + c];
//             blocks [2048,2480) split weight to bf16 hi/lo, pre-swizzled
// ---------------------------------------------------------------------------
__global__ __launch_bounds__(256) void prep_kernel(const float* __restrict__ x,
                                                   const float* __restrict__ w) {
    const int b = blockIdx.x;
    if (b < 2048) {
        __shared__ float tile[32][33];
        const int sbase = (b & 1023) * 32;
        const int cbase = (b >> 10) * 32;
        const int tx = threadIdx.x & 31, ty = threadIdx.x >> 5;
#pragma unroll
        for (int i = 0; i < 4; ++i) {
            const int c = ty + i * 8;
            tile[c][tx] = x[(cbase + c) * HWL + sbase + tx];
        }
        __syncthreads();
#pragma unroll
        for (int i = 0; i < 4; ++i) {
            const int s = ty + i * 8;
            g_xTp[PAD_LO + (sbase + s) * CDIM + cbase + tx] = tile[tx][s];
        }
    } else {
        const int tid = (b - 2048) * 256 + threadIdx.x;   // < 27*4096 exactly
        const int k   = tid >> 12;
        const int rem = tid & 4095;
        const int co  = rem >> 6;
        const int c   = rem & 63;
        const float v = w[(co * CDIM + c) * KPROD + k];
        const __nv_bfloat16 b0 = __float2bfloat16_rn(v);
        const float r = v - __bfloat162float(b0);
        const __nv_bfloat16 b1 = __float2bfloat16_rn(r);
        const uint32_t off = co * 128 + c * 2;            // row=co, 128B/row
        const uint32_t sw  = off ^ ((off >> 3) & 0x70);   // SW128
        *(__nv_bfloat16*)(g_wb + k * 16384 + sw)        = b0;
        *(__nv_bfloat16*)(g_wb + k * 16384 + 8192 + sw) = b1;
    }
}

// stage one tap's 16KB weight slab (b0|b1) via cp.async (identity copy)
__device__ __forceinline__ void stage_w(uint32_t dst, int k, int t) {
    const char* src = (const char*)g_wb + k * 16384 + t * 16;
    const uint32_t d = dst + t * 16;
#pragma unroll
    for (int i = 0; i < 4; ++i)
        asm volatile("cp.async.cg.shared.global [%0], [%1], 16;"
                     :: "r"(d + i * 4096), "l"(src + i * 4096) : "memory");
    asm volatile("cp.async.commit_group;");
}

#define ACC8(wt, p0, p1)                                                     \
    do { const float _w = (wt);                                              \
         v0 += _w * (p0).x; v1 += _w * (p0).y;                               \
         v2 += _w * (p0).z; v3 += _w * (p0).w;                               \
         v4 += _w * (p1).x; v5 += _w * (p1).y;                               \
         v6 += _w * (p1).z; v7 += _w * (p1).w; } while (0)

// ---------------------------------------------------------------------------
// Gather one tap into an A buffer. Branchless:
//   8 lanes per position (lane8 -> 8 channels), 4 positions per warp pass.
//   Validity folded into 1-D weights; addressing clamped into padded volume.
//   8 corner loads are constant offsets off one base ptr -> batched MLP.
// ---------------------------------------------------------------------------
__device__ __forceinline__ void gather_tap(
    char* smem, uint32_t abase, int k,
    const float* __restrict__ offset, const float* __restrict__ mask,
    int myp, int pw, int grp, int lane8, int pbase)
{
    const int ki = k / 9;
    const int kj = (k % 9) / 3;
    const int kk = k % 3;

    const float r_oh = offset[(k * 3 + 0) * HWL + myp];
    const float r_ow = offset[(k * 3 + 1) * HWL + myp];
    const float r_ol = offset[(k * 3 + 2) * HWL + myp];
    const float r_m  = mask[k * HWL + myp];

#pragma unroll 2
    for (int iter = 0; iter < 4; ++iter) {
        const int idx = iter * 4 + grp;
        const int p   = pw + idx;
        const int pg  = pbase + p;
        const int pl  = pg & 31;
        const int pwo = (pg >> 5) & 31;
        const int pho = pg >> 10;

        const float och = __shfl_sync(0xffffffffu, r_oh, idx);
        const float ocw = __shfl_sync(0xffffffffu, r_ow, idx);
        const float ocl = __shfl_sync(0xffffffffu, r_ol, idx);
        const float m   = __shfl_sync(0xffffffffu, r_m,  idx);

        const float ch = och + (float)(pho - 1 + ki);
        const float cw = ocw + (float)(pwo - 1 + kj);
        const float cl = ocl + (float)(pl - 1 + kk);

        const float hf = floorf(ch), wf = floorf(cw), lf = floorf(cl);
        int h0 = (int)hf, w0 = (int)wf, l0 = (int)lf;
        const float fh = ch - hf, fw = cw - wf, fl = cl - lf;

        // validity folded into 1-D weights (zero kills OOB corners)
        const float wh0 = ((unsigned)h0 < 32u)       ? 1.f - fh : 0.f;
        const float wh1 = ((unsigned)(h0 + 1) < 32u) ? fh       : 0.f;
        const float ww0 = ((unsigned)w0 < 32u)       ? 1.f - fw : 0.f;
        const float ww1 = ((unsigned)(w0 + 1) < 32u) ? fw       : 0.f;
        const float wl0 = ((unsigned)l0 < 32u)       ? 1.f - fl : 0.f;
        const float wl1 = ((unsigned)(l0 + 1) < 32u) ? fl       : 0.f;

        // clamp for ADDRESSING only (weights already zero outside volume)
        h0 = max(-8, min(h0, 40));
        w0 = max(-8, min(w0, 40));
        l0 = max(-8, min(l0, 40));
        const int sidx = ((h0 * 32 + w0) * 32 + l0) * CDIM + lane8 * 8;
        const float* bp = g_xTp + (PAD_LO + sidx);

        const float w00 = wh0 * ww0, w01 = wh0 * ww1;
        const float w10 = wh1 * ww0, w11 = wh1 * ww1;

        float v0 = 0.f, v1 = 0.f, v2 = 0.f, v3 = 0.f;
        float v4 = 0.f, v5 = 0.f, v6 = 0.f, v7 = 0.f;

        // corners dh = 0 (4 corners x 2 float4, batched loads)
        {
            const float4 a0 = *(const float4*)(bp + 0),    a1 = *(const float4*)(bp + 4);
            const float4 b0 = *(const float4*)(bp + 64),   b1 = *(const float4*)(bp + 68);
            const float4 c0 = *(const float4*)(bp + 2048), c1 = *(const float4*)(bp + 2052);
            const float4 d0 = *(const float4*)(bp + 2112), d1 = *(const float4*)(bp + 2116);
            ACC8(w00 * wl0, a0, a1);
            ACC8(w00 * wl1, b0, b1);
            ACC8(w01 * wl0, c0, c1);
            ACC8(w01 * wl1, d0, d1);
        }
        // corners dh = 1
        {
            const float* bq = bp + 65536;
            const float4 a0 = *(const float4*)(bq + 0),    a1 = *(const float4*)(bq + 4);
            const float4 b0 = *(const float4*)(bq + 64),   b1 = *(const float4*)(bq + 68);
            const float4 c0 = *(const float4*)(bq + 2048), c1 = *(const float4*)(bq + 2052);
            const float4 d0 = *(const float4*)(bq + 2112), d1 = *(const float4*)(bq + 2116);
            ACC8(w10 * wl0, a0, a1);
            ACC8(w10 * wl1, b0, b1);
            ACC8(w11 * wl0, c0, c1);
            ACC8(w11 * wl1, d0, d1);
        }

        v0 *= m; v1 *= m; v2 *= m; v3 *= m;
        v4 *= m; v5 *= m; v6 *= m; v7 *= m;

        // packed bf16 hi/lo split
        const __nv_bfloat162 h01 = __floats2bfloat162_rn(v0, v1);
        const __nv_bfloat162 h23 = __floats2bfloat162_rn(v2, v3);
        const __nv_bfloat162 h45 = __floats2bfloat162_rn(v4, v5);
        const __nv_bfloat162 h67 = __floats2bfloat162_rn(v6, v7);
        const float2 f01 = __bfloat1622float2(h01);
        const float2 f23 = __bfloat1622float2(h23);
        const float2 f45 = __bfloat1622float2(h45);
        const float2 f67 = __bfloat1622float2(h67);
        const __nv_bfloat162 l01 = __floats2bfloat162_rn(v0 - f01.x, v1 - f01.y);
        const __nv_bfloat162 l23 = __floats2bfloat162_rn(v2 - f23.x, v3 - f23.y);
        const __nv_bfloat162 l45 = __floats2bfloat162_rn(v4 - f45.x, v5 - f45.y);
        const __nv_bfloat162 l67 = __floats2bfloat162_rn(v6 - f67.x, v7 - f67.y);

        uint4 shi, slo;
        shi.x = *(const uint32_t*)&h01; shi.y = *(const uint32_t*)&h23;
        shi.z = *(const uint32_t*)&h45; shi.w = *(const uint32_t*)&h67;
        slo.x = *(const uint32_t*)&l01; slo.y = *(const uint32_t*)&l23;
        slo.z = *(const uint32_t*)&l45; slo.w = *(const uint32_t*)&l67;

        // SW128-swizzled STS.128: row = p (128B), cols = 8 channels (16B)
        const uint32_t off = (uint32_t)(p * 128 + lane8 * 16);
        const uint32_t sw  = off ^ (uint32_t)((p & 7) << 4);
        *(uint4*)(smem + abase + sw)        = shi;
        *(uint4*)(smem + abase + A_LO + sw) = slo;
    }
}

// ---------------------------------------------------------------------------
// Fused deformable conv3d, software-pipelined:
//   iteration k: gather(tap k+1 -> A buf (k+1)&1) | GEMM(tap k from buf k&1)
//   single __syncthreads per iteration.
// ---------------------------------------------------------------------------
__global__ __launch_bounds__(256, 2)
void deform_conv3d_kernel(const float* __restrict__ offset,
                          const float* __restrict__ mask,
                          float* __restrict__ out) {
    extern __shared__ char smem[];
    const uint32_t sb = s2u(smem);

    const int t      = threadIdx.x;
    const int lane   = t & 31;
    const int warp   = t >> 5;
    const int lane8  = lane & 7;
    const int grp    = lane >> 3;
    const int pbase  = blockIdx.x * P_TILE;
    const int pw     = warp * 16;
    const int myp    = pbase + pw + (lane & 15);

    // GEMM warp tile: 4(p) x 2(co) warp grid, 32p x 32co per warp
    const int pblk = (warp & 3) * 32;
    const int cblk = (warp >> 2) * 32;

    const int lrr = lane & 7;
    const int a_row_off = lrr + ((lane >> 3) & 1) * 8;
    const int a_colh    = (lane >> 4) & 1;
    const int b_row_off = lrr + ((lane >> 4) & 1) * 8;
    const int b_colh    = (lane >> 3) & 1;

    const uint32_t a_sx[2] = { (uint32_t)(((pblk + 0 * 16 + a_row_off) & 7) << 4),
                               (uint32_t)(((pblk + 1 * 16 + a_row_off) & 7) << 4) };
    const uint32_t b_sx[2] = { (uint32_t)(((cblk + 0 * 16 + b_row_off) & 7) << 4),
                               (uint32_t)(((cblk + 1 * 16 + b_row_off) & 7) << 4) };
    const uint32_t a_rb[2] = { (uint32_t)((pblk + 0 * 16 + a_row_off) * 128),
                               (uint32_t)((pblk + 1 * 16 + a_row_off) * 128) };
    const uint32_t b_rb[2] = { (uint32_t)((cblk + 0 * 16 + b_row_off) * 128),
                               (uint32_t)((cblk + 1 * 16 + b_row_off) * 128) };

    float acc[2][4][4];
#pragma unroll
    for (int i = 0; i < 2; ++i)
#pragma unroll
        for (int j = 0; j < 4; ++j)
#pragma unroll
            for (int q = 0; q < 4; ++q) acc[i][j][q] = 0.f;

    // prologue: weights tap 0 + gather tap 0 into buffer 0
    stage_w(sb + OFF_W, 0, t);
    gather_tap(smem, OFF_A, 0, offset, mask, myp, pw, grp, lane8, pbase);
    __syncthreads();

    for (int k = 0; k < KPROD; ++k) {
        if (k < KPROD - 1) {
            stage_w(sb + OFF_W + (uint32_t)((k + 1) & 1) * 16384, k + 1, t);
            gather_tap(smem, OFF_A + (uint32_t)((k + 1) & 1) * A_BUF_SZ, k + 1,
                       offset, mask, myp, pw, grp, lane8, pbase);
        }

        if (k == KPROD - 1)
            asm volatile("cp.async.wait_group 0;" ::: "memory");
        else
            asm volatile("cp.async.wait_group 1;" ::: "memory");

        // ---- GEMM: tap k ----
        const uint32_t wS  = sb + OFF_W + (uint32_t)(k & 1) * 16384;
        const uint32_t a0b = sb + OFF_A + (uint32_t)(k & 1) * A_BUF_SZ;
        const uint32_t a1b = a0b + A_LO;
#pragma unroll
        for (int ks = 0; ks < 4; ++ks) {
            const uint32_t cbA = ((uint32_t)(ks * 32 + a_colh * 16));
            const uint32_t cbB = ((uint32_t)(ks * 32 + b_colh * 16));
            uint32_t A0[2][4], A1[2][4], B0[2][4], B1[2][4];
#pragma unroll
            for (int pt = 0; pt < 2; ++pt) {
                const uint32_t ad = a_rb[pt] + (cbA ^ a_sx[pt]);
                ldmx4(A0[pt], a0b + ad);
                ldmx4(A1[pt], a1b + ad);
            }
#pragma unroll
            for (int b2 = 0; b2 < 2; ++b2) {
                const uint32_t bd = b_rb[b2] + (cbB ^ b_sx[b2]);
                ldmx4(B0[b2], wS + bd);
                ldmx4(B1[b2], wS + 8192 + bd);
            }
#pragma unroll
            for (int pt = 0; pt < 2; ++pt)
#pragma unroll
                for (int bt = 0; bt < 4; ++bt) {
                    const int b2 = bt >> 1, hh = (bt & 1) * 2;
                    mma16816(acc[pt][bt], A0[pt], B0[b2][hh], B0[b2][hh + 1]);
                    mma16816(acc[pt][bt], A0[pt], B1[b2][hh], B1[b2][hh + 1]);
                    mma16816(acc[pt][bt], A1[pt], B0[b2][hh], B0[b2][hh + 1]);
                }
        }
        __syncthreads();
    }

    // ---- epilogue: D frag layout -> out[co][p] ----
    const int prow = lane >> 2;
    const int pcol = (lane & 3) * 2;
#pragma unroll
    for (int pt = 0; pt < 2; ++pt)
#pragma unroll
        for (int bt = 0; bt < 4; ++bt) {
            const int p0 = pbase + pblk + pt * 16 + prow;
            const int co = cblk + bt * 8 + pcol;
            out[(size_t)co * HWL + p0]           = acc[pt][bt][0];
            out[(size_t)(co + 1) * HWL + p0]     = acc[pt][bt][1];
            out[(size_t)co * HWL + p0 + 8]       = acc[pt][bt][2];
            out[(size_t)(co + 1) * HWL + p0 + 8] = acc[pt][bt][3];
        }
}

// ---------------------------------------------------------------------------
extern "C" void kernel_launch(void* const* d_in, const int* in_sizes, int n_in,
                              void* d_out, int out_size) {
    const float* x = nullptr;
    const float* offset = nullptr;
    const float* mask = nullptr;
    const float* weight = nullptr;
    for (int i = 0; i < n_in; ++i) {
        switch (in_sizes[i]) {
            case 2097152: x      = (const float*)d_in[i]; break;  // [1,64,32,32,32]
            case 2654208: offset = (const float*)d_in[i]; break;  // [1,81,32,32,32]
            case 884736:  mask   = (const float*)d_in[i]; break;  // [1,27,32,32,32]
            case 110592:  weight = (const float*)d_in[i]; break;  // [64,64,3,3,3]
        }
    }

    static bool s_attr_done = false;
    if (!s_attr_done) {
        cudaFuncSetAttribute(deform_conv3d_kernel,
                             cudaFuncAttributeMaxDynamicSharedMemorySize, SMEM_BYTES);
        s_attr_done = true;
    }

    prep_kernel<<<2480, 256>>>(x, weight);
    deform_conv3d_kernel<<<HWL / P_TILE, 256, SMEM_BYTES>>>(offset, mask, (float*)d_out);
}

// round 11
// speedup vs baseline: 1.1954x; 1.1954x over previous
#include <cuda_runtime.h>
#include <cuda_bf16.h>
#include <cstdint>

#define HWL    32768          // 32*32*32 spatial positions
#define CDIM   64             // in channels == out channels
#define KPROD  27             // 3*3*3 taps
#define P_TILE 128            // output positions per CTA (= GEMM M)

// Padded channels-last x: guard bands let the gather skip ALL bounds checks
// (validity folded into interpolation weights; pads are zero — harmless reads).
// Addressing clamp range [-8,40] per dim -> idx in (-541184, 2773632).
#define PAD_LO 560000
#define PAD_HI 700000
__device__ __align__(16) float g_xTp[PAD_LO + HWL * CDIM + PAD_HI];
__device__ __align__(16) unsigned char g_wb[KPROD * 16384];
// per tap: [b0: 8KB][b1: 8KB]; rows = cout (128B each, 64 c x bf16), SW128-swizzled

__device__ __forceinline__ uint32_t s2u(const void* p) {
    uint32_t a;
    asm("{ .reg .u64 t; cvta.to.shared.u64 t, %1; cvt.u32.u64 %0, t; }"
        : "=r"(a) : "l"(p));
    return a;
}

__device__ __forceinline__ void ldmx4(uint32_t* r, uint32_t addr) {
    asm volatile("ldmatrix.sync.aligned.m8n8.x4.shared.b16 {%0,%1,%2,%3}, [%4];"
                 : "=r"(r[0]), "=r"(r[1]), "=r"(r[2]), "=r"(r[3]) : "r"(addr));
}

__device__ __forceinline__ void mma16816(float* d, const uint32_t* a,
                                         uint32_t b0, uint32_t b1) {
    asm volatile(
        "mma.sync.aligned.m16n8k16.row.col.f32.bf16.bf16.f32 "
        "{%0,%1,%2,%3}, {%4,%5,%6,%7}, {%8,%9}, {%0,%1,%2,%3};"
        : "+f"(d[0]), "+f"(d[1]), "+f"(d[2]), "+f"(d[3])
        : "r"(a[0]), "r"(a[1]), "r"(a[2]), "r"(a[3]), "r"(b0), "r"(b1));
}

// smem layout (bytes from dynamic smem base)
#define OFF_A      0
#define A_BUF_SZ   32768
#define A_LO       16384
#define OFF_W      65536
#define SMEM_BYTES (OFF_W + 32768)   // 96 KB -> 2 CTAs/SM

// ---------------------------------------------------------------------------
// Fused prep: blocks [0,2048) transpose x -> g_xTp[PAD_LO + s*64 + c];
//             blocks [2048,2480) split weight to bf16 hi/lo, pre-swizzled
// ---------------------------------------------------------------------------
__global__ __launch_bounds__(256) void prep_kernel(const float* __restrict__ x,
                                                   const float* __restrict__ w) {
    const int b = blockIdx.x;
    if (b < 2048) {
        __shared__ float tile[32][33];
        const int sbase = (b & 1023) * 32;
        const int cbase = (b >> 10) * 32;
        const int tx = threadIdx.x & 31, ty = threadIdx.x >> 5;
#pragma unroll
        for (int i = 0; i < 4; ++i) {
            const int c = ty + i * 8;
            tile[c][tx] = x[(cbase + c) * HWL + sbase + tx];
        }
        __syncthreads();
#pragma unroll
        for (int i = 0; i < 4; ++i) {
            const int s = ty + i * 8;
            g_xTp[PAD_LO + (sbase + s) * CDIM + cbase + tx] = tile[tx][s];
        }
    } else {
        const int tid = (b - 2048) * 256 + threadIdx.x;   // < 27*4096 exactly
        const int k   = tid >> 12;
        const int rem = tid & 4095;
        const int co  = rem >> 6;
        const int c   = rem & 63;
        const float v = w[(co * CDIM + c) * KPROD + k];
        const __nv_bfloat16 b0 = __float2bfloat16_rn(v);
        const float r = v - __bfloat162float(b0);
        const __nv_bfloat16 b1 = __float2bfloat16_rn(r);
        const uint32_t off = co * 128 + c * 2;            // row=co, 128B/row
        const uint32_t sw  = off ^ ((off >> 3) & 0x70);   // SW128
        *(__nv_bfloat16*)(g_wb + k * 16384 + sw)        = b0;
        *(__nv_bfloat16*)(g_wb + k * 16384 + 8192 + sw) = b1;
    }
}

// stage one tap's 16KB weight slab (b0|b1) via cp.async (identity copy)
__device__ __forceinline__ void stage_w(uint32_t dst, int k, int t) {
    const char* src = (const char*)g_wb + k * 16384 + t * 16;
    const uint32_t d = dst + t * 16;
#pragma unroll
    for (int i = 0; i < 4; ++i)
        asm volatile("cp.async.cg.shared.global [%0], [%1], 16;"
                     :: "r"(d + i * 4096), "l"(src + i * 4096) : "memory");
    asm volatile("cp.async.commit_group;");
}

// ---------------------------------------------------------------------------
// Gather one tap into an A buffer.
//   Memory shape (round-7, coalesced): 16 lanes per position, 1 float4/lane
//     (16 x 16B contiguous per corner), 2 positions per warp pass.
//   Scalar shape (round-8, branchless): validity folded into 1-D weights,
//     addressing clamped into padded volume, 8 constant-offset corner loads
//     issued back-to-back (MLP=8), packed bf16 hi/lo split.
// ---------------------------------------------------------------------------
__device__ __forceinline__ void gather_tap(
    char* smem, uint32_t abase, int k,
    const float* __restrict__ offset, const float* __restrict__ mask,
    int myp, int pw, int sub, int lane16, int pbase)
{
    const int ki = k / 9;
    const int kj = (k % 9) / 3;
    const int kk = k % 3;

    const float r_oh = offset[(k * 3 + 0) * HWL + myp];
    const float r_ow = offset[(k * 3 + 1) * HWL + myp];
    const float r_ol = offset[(k * 3 + 2) * HWL + myp];
    const float r_m  = mask[k * HWL + myp];

#pragma unroll 2
    for (int iter = 0; iter < 8; ++iter) {
        const int idx = iter * 2 + sub;
        const int p   = pw + idx;
        const int pg  = pbase + p;
        const int pl  = pg & 31;
        const int pwo = (pg >> 5) & 31;
        const int pho = pg >> 10;

        const float och = __shfl_sync(0xffffffffu, r_oh, idx);
        const float ocw = __shfl_sync(0xffffffffu, r_ow, idx);
        const float ocl = __shfl_sync(0xffffffffu, r_ol, idx);
        const float m   = __shfl_sync(0xffffffffu, r_m,  idx);

        const float ch = och + (float)(pho - 1 + ki);
        const float cw = ocw + (float)(pwo - 1 + kj);
        const float cl = ocl + (float)(pl - 1 + kk);

        const float hf = floorf(ch), wf = floorf(cw), lf = floorf(cl);
        int h0 = (int)hf, w0 = (int)wf, l0 = (int)lf;
        const float fh = ch - hf, fw = cw - wf, fl = cl - lf;

        // validity folded into 1-D weights (zero kills OOB corners)
        const float wh0 = ((unsigned)h0 < 32u)       ? 1.f - fh : 0.f;
        const float wh1 = ((unsigned)(h0 + 1) < 32u) ? fh       : 0.f;
        const float ww0 = ((unsigned)w0 < 32u)       ? 1.f - fw : 0.f;
        const float ww1 = ((unsigned)(w0 + 1) < 32u) ? fw       : 0.f;
        const float wl0 = ((unsigned)l0 < 32u)       ? 1.f - fl : 0.f;
        const float wl1 = ((unsigned)(l0 + 1) < 32u) ? fl       : 0.f;

        // clamp for ADDRESSING only (weights already zero outside volume)
        h0 = max(-8, min(h0, 40));
        w0 = max(-8, min(w0, 40));
        l0 = max(-8, min(l0, 40));
        const float* bp = g_xTp + (PAD_LO +
            ((h0 * 32 + w0) * 32 + l0) * CDIM + lane16 * 4);

        // 8 corner loads, constant offsets, back-to-back (coalesced 256B each)
        const float4 c000 = *(const float4*)(bp + 0);
        const float4 c001 = *(const float4*)(bp + 64);
        const float4 c010 = *(const float4*)(bp + 2048);
        const float4 c011 = *(const float4*)(bp + 2112);
        const float4 c100 = *(const float4*)(bp + 65536);
        const float4 c101 = *(const float4*)(bp + 65600);
        const float4 c110 = *(const float4*)(bp + 67584);
        const float4 c111 = *(const float4*)(bp + 67648);

        const float w00 = wh0 * ww0, w01 = wh0 * ww1;
        const float w10 = wh1 * ww0, w11 = wh1 * ww1;
        const float k000 = w00 * wl0, k001 = w00 * wl1;
        const float k010 = w01 * wl0, k011 = w01 * wl1;
        const float k100 = w10 * wl0, k101 = w10 * wl1;
        const float k110 = w11 * wl0, k111 = w11 * wl1;

        float v0 = k000 * c000.x + k001 * c001.x + k010 * c010.x + k011 * c011.x
                 + k100 * c100.x + k101 * c101.x + k110 * c110.x + k111 * c111.x;
        float v1 = k000 * c000.y + k001 * c001.y + k010 * c010.y + k011 * c011.y
                 + k100 * c100.y + k101 * c101.y + k110 * c110.y + k111 * c111.y;
        float v2 = k000 * c000.z + k001 * c001.z + k010 * c010.z + k011 * c011.z
                 + k100 * c100.z + k101 * c101.z + k110 * c110.z + k111 * c111.z;
        float v3 = k000 * c000.w + k001 * c001.w + k010 * c010.w + k011 * c011.w
                 + k100 * c100.w + k101 * c101.w + k110 * c110.w + k111 * c111.w;

        v0 *= m; v1 *= m; v2 *= m; v3 *= m;

        // packed bf16 hi/lo split
        const __nv_bfloat162 h01 = __floats2bfloat162_rn(v0, v1);
        const __nv_bfloat162 h23 = __floats2bfloat162_rn(v2, v3);
        const float2 f01 = __bfloat1622float2(h01);
        const float2 f23 = __bfloat1622float2(h23);
        const __nv_bfloat162 l01 = __floats2bfloat162_rn(v0 - f01.x, v1 - f01.y);
        const __nv_bfloat162 l23 = __floats2bfloat162_rn(v2 - f23.x, v3 - f23.y);

        uint2 shi, slo;
        shi.x = *(const uint32_t*)&h01; shi.y = *(const uint32_t*)&h23;
        slo.x = *(const uint32_t*)&l01; slo.y = *(const uint32_t*)&l23;

        // SW128-swizzled STS.64: row = p (128B), cols = 4 channels (8B)
        const uint32_t off = (uint32_t)(p * 128 + lane16 * 8);
        const uint32_t sw  = off ^ (uint32_t)((p & 7) << 4);
        *(uint2*)(smem + abase + sw)        = shi;
        *(uint2*)(smem + abase + A_LO + sw) = slo;
    }
}

// ---------------------------------------------------------------------------
// Fused deformable conv3d, software-pipelined:
//   iteration k: gather(tap k+1 -> A buf (k+1)&1) | GEMM(tap k from buf k&1)
//   single __syncthreads per iteration.
// ---------------------------------------------------------------------------
__global__ __launch_bounds__(256, 2)
void deform_conv3d_kernel(const float* __restrict__ offset,
                          const float* __restrict__ mask,
                          float* __restrict__ out) {
    extern __shared__ char smem[];
    const uint32_t sb = s2u(smem);

    const int t      = threadIdx.x;
    const int lane   = t & 31;
    const int warp   = t >> 5;
    const int lane16 = lane & 15;
    const int sub    = lane >> 4;
    const int pbase  = blockIdx.x * P_TILE;
    const int pw     = warp * 16;
    const int myp    = pbase + pw + lane16;

    // GEMM warp tile: 4(p) x 2(co) warp grid, 32p x 32co per warp
    const int pblk = (warp & 3) * 32;
    const int cblk = (warp >> 2) * 32;

    const int lrr = lane & 7;
    const int a_row_off = lrr + ((lane >> 3) & 1) * 8;
    const int a_colh    = (lane >> 4) & 1;
    const int b_row_off = lrr + ((lane >> 4) & 1) * 8;
    const int b_colh    = (lane >> 3) & 1;

    const uint32_t a_sx[2] = { (uint32_t)(((pblk + 0 * 16 + a_row_off) & 7) << 4),
                               (uint32_t)(((pblk + 1 * 16 + a_row_off) & 7) << 4) };
    const uint32_t b_sx[2] = { (uint32_t)(((cblk + 0 * 16 + b_row_off) & 7) << 4),
                               (uint32_t)(((cblk + 1 * 16 + b_row_off) & 7) << 4) };
    const uint32_t a_rb[2] = { (uint32_t)((pblk + 0 * 16 + a_row_off) * 128),
                               (uint32_t)((pblk + 1 * 16 + a_row_off) * 128) };
    const uint32_t b_rb[2] = { (uint32_t)((cblk + 0 * 16 + b_row_off) * 128),
                               (uint32_t)((cblk + 1 * 16 + b_row_off) * 128) };

    float acc[2][4][4];
#pragma unroll
    for (int i = 0; i < 2; ++i)
#pragma unroll
        for (int j = 0; j < 4; ++j)
#pragma unroll
            for (int q = 0; q < 4; ++q) acc[i][j][q] = 0.f;

    // prologue: weights tap 0 + gather tap 0 into buffer 0
    stage_w(sb + OFF_W, 0, t);
    gather_tap(smem, OFF_A, 0, offset, mask, myp, pw, sub, lane16, pbase);
    __syncthreads();

    for (int k = 0; k < KPROD; ++k) {
        if (k < KPROD - 1) {
            stage_w(sb + OFF_W + (uint32_t)((k + 1) & 1) * 16384, k + 1, t);
            gather_tap(smem, OFF_A + (uint32_t)((k + 1) & 1) * A_BUF_SZ, k + 1,
                       offset, mask, myp, pw, sub, lane16, pbase);
        }

        if (k == KPROD - 1)
            asm volatile("cp.async.wait_group 0;" ::: "memory");
        else
            asm volatile("cp.async.wait_group 1;" ::: "memory");

        // ---- GEMM: tap k ----
        const uint32_t wS  = sb + OFF_W + (uint32_t)(k & 1) * 16384;
        const uint32_t a0b = sb + OFF_A + (uint32_t)(k & 1) * A_BUF_SZ;
        const uint32_t a1b = a0b + A_LO;
#pragma unroll
        for (int ks = 0; ks < 4; ++ks) {
            const uint32_t cbA = ((uint32_t)(ks * 32 + a_colh * 16));
            const uint32_t cbB = ((uint32_t)(ks * 32 + b_colh * 16));
            uint32_t A0[2][4], A1[2][4], B0[2][4], B1[2][4];
#pragma unroll
            for (int pt = 0; pt < 2; ++pt) {
                const uint32_t ad = a_rb[pt] + (cbA ^ a_sx[pt]);
                ldmx4(A0[pt], a0b + ad);
                ldmx4(A1[pt], a1b + ad);
            }
#pragma unroll
            for (int b2 = 0; b2 < 2; ++b2) {
                const uint32_t bd = b_rb[b2] + (cbB ^ b_sx[b2]);
                ldmx4(B0[b2], wS + bd);
                ldmx4(B1[b2], wS + 8192 + bd);
            }
#pragma unroll
            for (int pt = 0; pt < 2; ++pt)
#pragma unroll
                for (int bt = 0; bt < 4; ++bt) {
                    const int b2 = bt >> 1, hh = (bt & 1) * 2;
                    mma16816(acc[pt][bt], A0[pt], B0[b2][hh], B0[b2][hh + 1]);
                    mma16816(acc[pt][bt], A0[pt], B1[b2][hh], B1[b2][hh + 1]);
                    mma16816(acc[pt][bt], A1[pt], B0[b2][hh], B0[b2][hh + 1]);
                }
        }
        __syncthreads();
    }

    // ---- epilogue: D frag layout -> out[co][p] ----
    const int prow = lane >> 2;
    const int pcol = (lane & 3) * 2;
#pragma unroll
    for (int pt = 0; pt < 2; ++pt)
#pragma unroll
        for (int bt = 0; bt < 4; ++bt) {
            const int p0 = pbase + pblk + pt * 16 + prow;
            const int co = cblk + bt * 8 + pcol;
            out[(size_t)co * HWL + p0]           = acc[pt][bt][0];
            out[(size_t)(co + 1) * HWL + p0]     = acc[pt][bt][1];
            out[(size_t)co * HWL + p0 + 8]       = acc[pt][bt][2];
            out[(size_t)(co + 1) * HWL + p0 + 8] = acc[pt][bt][3];
        }
}

// ---------------------------------------------------------------------------
extern "C" void kernel_launch(void* const* d_in, const int* in_sizes, int n_in,
                              void* d_out, int out_size) {
    const float* x = nullptr;
    const float* offset = nullptr;
    const float* mask = nullptr;
    const float* weight = nullptr;
    for (int i = 0; i < n_in; ++i) {
        switch (in_sizes[i]) {
            case 2097152: x      = (const float*)d_in[i]; break;  // [1,64,32,32,32]
            case 2654208: offset = (const float*)d_in[i]; break;  // [1,81,32,32,32]
            case 884736:  mask   = (const float*)d_in[i]; break;  // [1,27,32,32,32]
            case 110592:  weight = (const float*)d_in[i]; break;  // [64,64,3,3,3]
        }
    }

    static bool s_attr_done = false;
    if (!s_attr_done) {
        cudaFuncSetAttribute(deform_conv3d_kernel,
                             cudaFuncAttributeMaxDynamicSharedMemorySize, SMEM_BYTES);
        s_attr_done = true;
    }

    prep_kernel<<<2480, 256>>>(x, weight);
    deform_conv3d_kernel<<<HWL / P_TILE, 256, SMEM_BYTES>>>(offset, mask, (float*)d_out);
}

// round 12
// speedup vs baseline: 1.3136x; 1.0989x over previous
#include <cuda_runtime.h>
#include <cuda_bf16.h>
#include <cuda_fp16.h>
#include <cstdint>

#define HWL    32768          // 32*32*32 spatial positions
#define CDIM   64             // in channels == out channels
#define KPROD  27             // 3*3*3 taps
#define P_TILE 128            // output positions per CTA (= GEMM M)

// Padded channels-last x in fp16: guard bands let the gather skip ALL bounds
// checks (validity folded into weights; pads are zero — harmless reads).
// Addressing clamp range [-8,40] per dim -> element idx in (-541184, 2773700).
#define PAD_LO 560000
#define PAD_HI 700000
__device__ __align__(16) __half g_xhp[PAD_LO + HWL * CDIM + PAD_HI];
__device__ __align__(16) unsigned char g_wb[KPROD * 16384];
// per tap: [b0: 8KB][b1: 8KB]; rows = cout (128B each, 64 c x bf16), SW128-swizzled

__device__ __forceinline__ uint32_t s2u(const void* p) {
    uint32_t a;
    asm("{ .reg .u64 t; cvta.to.shared.u64 t, %1; cvt.u32.u64 %0, t; }"
        : "=r"(a) : "l"(p));
    return a;
}

__device__ __forceinline__ void ldmx4(uint32_t* r, uint32_t addr) {
    asm volatile("ldmatrix.sync.aligned.m8n8.x4.shared.b16 {%0,%1,%2,%3}, [%4];"
                 : "=r"(r[0]), "=r"(r[1]), "=r"(r[2]), "=r"(r[3]) : "r"(addr));
}

__device__ __forceinline__ void mma16816(float* d, const uint32_t* a,
                                         uint32_t b0, uint32_t b1) {
    asm volatile(
        "mma.sync.aligned.m16n8k16.row.col.f32.bf16.bf16.f32 "
        "{%0,%1,%2,%3}, {%4,%5,%6,%7}, {%8,%9}, {%0,%1,%2,%3};"
        : "+f"(d[0]), "+f"(d[1]), "+f"(d[2]), "+f"(d[3])
        : "r"(a[0]), "r"(a[1]), "r"(a[2]), "r"(a[3]), "r"(b0), "r"(b1));
}

// smem layout (bytes from dynamic smem base)
#define OFF_A      0
#define A_BUF_SZ   32768
#define A_LO       16384
#define OFF_W      65536
#define OFF_META   (OFF_W + 32768)          // per-position metadata: 128 x 48B
#define SMEM_BYTES (OFF_META + 128 * 48)    // 104448 -> 2 CTAs/SM (204 KB)

// ---------------------------------------------------------------------------
// Fused prep: blocks [0,2048) transpose x -> g_xhp[PAD_LO + s*64 + c] (fp16);
//             blocks [2048,2480) split weight to bf16 hi/lo, pre-swizzled
// ---------------------------------------------------------------------------
__global__ __launch_bounds__(256) void prep_kernel(const float* __restrict__ x,
                                                   const float* __restrict__ w) {
    const int b = blockIdx.x;
    if (b < 2048) {
        __shared__ float tile[32][33];
        const int sbase = (b & 1023) * 32;
        const int cbase = (b >> 10) * 32;
        const int tx = threadIdx.x & 31, ty = threadIdx.x >> 5;
#pragma unroll
        for (int i = 0; i < 4; ++i) {
            const int c = ty + i * 8;
            tile[c][tx] = x[(cbase + c) * HWL + sbase + tx];
        }
        __syncthreads();
#pragma unroll
        for (int i = 0; i < 4; ++i) {
            const int s = ty + i * 8;
            g_xhp[PAD_LO + (sbase + s) * CDIM + cbase + tx] =
                __float2half_rn(tile[tx][s]);
        }
    } else {
        const int tid = (b - 2048) * 256 + threadIdx.x;   // < 27*4096 exactly
        const int k   = tid >> 12;
        const int rem = tid & 4095;
        const int co  = rem >> 6;
        const int c   = rem & 63;
        const float v = w[(co * CDIM + c) * KPROD + k];
        const __nv_bfloat16 b0 = __float2bfloat16_rn(v);
        const float r = v - __bfloat162float(b0);
        const __nv_bfloat16 b1 = __float2bfloat16_rn(r);
        const uint32_t off = co * 128 + c * 2;            // row=co, 128B/row
        const uint32_t sw  = off ^ ((off >> 3) & 0x70);   // SW128
        *(__nv_bfloat16*)(g_wb + k * 16384 + sw)        = b0;
        *(__nv_bfloat16*)(g_wb + k * 16384 + 8192 + sw) = b1;
    }
}

// stage one tap's 16KB weight slab (b0|b1) via cp.async (identity copy)
__device__ __forceinline__ void stage_w(uint32_t dst, int k, int t) {
    const char* src = (const char*)g_wb + k * 16384 + t * 16;
    const uint32_t d = dst + t * 16;
#pragma unroll
    for (int i = 0; i < 4; ++i)
        asm volatile("cp.async.cg.shared.global [%0], [%1], 16;"
                     :: "r"(d + i * 4096), "l"(src + i * 4096) : "memory");
    asm volatile("cp.async.commit_group;");
}

// convert one corner (4 fp16 channels) and accumulate with weight kw
#define CVTACC(u, kw)                                                        \
    do { const float2 _a = __half22float2(*(const __half2*)&(u).x);          \
         const float2 _b = __half22float2(*(const __half2*)&(u).y);          \
         const float _k = (kw);                                              \
         v0 += _k * _a.x; v1 += _k * _a.y;                                   \
         v2 += _k * _b.x; v3 += _k * _b.y; } while (0)

// ---------------------------------------------------------------------------
// Gather one tap into an A buffer.
//   Phase M (once per tap per warp): lanes compute per-position metadata —
//     8 corner weights (mask folded in) + base element index — stored to a
//     warp-private smem slice; __syncwarp orders store->read.
//   Phase G (8 passes x 2 positions): read metadata via broadcast LDS, issue
//     8 constant-offset fp16 corner loads (16 lanes x 8B = 128B contiguous),
//     convert+interp in fp32, bf16 hi/lo split, swizzled STS.
// ---------------------------------------------------------------------------
__device__ __forceinline__ void gather_tap(
    char* smem, uint32_t abase, int k,
    const float* __restrict__ offset, const float* __restrict__ mask,
    int pw, int sub, int lane16, int pbase)
{
    const int ki = k / 9;
    const int kj = (k % 9) / 3;
    const int kk = k % 3;

    // ---- Phase M: metadata for this warp's 16 positions ----
    {
        const int mp  = pw + lane16;          // position in tile
        const int pgm = pbase + mp;           // global position
        const int pl  = pgm & 31;
        const int pwo = (pgm >> 5) & 31;
        const int pho = pgm >> 10;

        const float och = offset[(k * 3 + 0) * HWL + pgm];
        const float ocw = offset[(k * 3 + 1) * HWL + pgm];
        const float ocl = offset[(k * 3 + 2) * HWL + pgm];
        const float m   = mask[k * HWL + pgm];

        const float ch = och + (float)(pho - 1 + ki);
        const float cw = ocw + (float)(pwo - 1 + kj);
        const float cl = ocl + (float)(pl - 1 + kk);

        const float hf = floorf(ch), wf = floorf(cw), lf = floorf(cl);
        int h0 = (int)hf, w0 = (int)wf, l0 = (int)lf;
        const float fh = ch - hf, fw = cw - wf, fl = cl - lf;

        const float wh0 = ((unsigned)h0 < 32u)       ? 1.f - fh : 0.f;
        const float wh1 = ((unsigned)(h0 + 1) < 32u) ? fh       : 0.f;
        const float ww0 = ((unsigned)w0 < 32u)       ? 1.f - fw : 0.f;
        const float ww1 = ((unsigned)(w0 + 1) < 32u) ? fw       : 0.f;
        const float wl0 = ((unsigned)l0 < 32u)       ? 1.f - fl : 0.f;
        const float wl1 = ((unsigned)(l0 + 1) < 32u) ? fl       : 0.f;

        h0 = max(-8, min(h0, 40));
        w0 = max(-8, min(w0, 40));
        l0 = max(-8, min(l0, 40));
        const int base = PAD_LO + ((h0 * 32 + w0) * 32 + l0) * CDIM;

        const float w00 = wh0 * ww0 * m, w01 = wh0 * ww1 * m;
        const float w10 = wh1 * ww0 * m, w11 = wh1 * ww1 * m;

        if ((lane16 | 0) == (threadIdx.x & 31)) {   // lanes 0..15 only
            char* mrow = smem + OFF_META + mp * 48;
            *(float4*)(mrow)      = make_float4(w00 * wl0, w00 * wl1,
                                                w01 * wl0, w01 * wl1);
            *(float4*)(mrow + 16) = make_float4(w10 * wl0, w10 * wl1,
                                                w11 * wl0, w11 * wl1);
            *(int*)(mrow + 32)    = base;
        }
    }
    __syncwarp();

    // ---- Phase G: gather using metadata ----
#pragma unroll 2
    for (int iter = 0; iter < 8; ++iter) {
        const int idx = iter * 2 + sub;
        const int p   = pw + idx;

        const char* mrow = smem + OFF_META + p * 48;
        const float4 ka = *(const float4*)(mrow);
        const float4 kb = *(const float4*)(mrow + 16);
        const int  base = *(const int*)(mrow + 32);

        const __half* bp = g_xhp + base + lane16 * 4;

        // 8 corner loads (fp16): constant offsets, back-to-back, 128B each
        const uint2 u000 = *(const uint2*)(bp + 0);
        const uint2 u001 = *(const uint2*)(bp + 64);
        const uint2 u010 = *(const uint2*)(bp + 2048);
        const uint2 u011 = *(const uint2*)(bp + 2112);
        const uint2 u100 = *(const uint2*)(bp + 65536);
        const uint2 u101 = *(const uint2*)(bp + 65600);
        const uint2 u110 = *(const uint2*)(bp + 67584);
        const uint2 u111 = *(const uint2*)(bp + 67648);

        float v0 = 0.f, v1 = 0.f, v2 = 0.f, v3 = 0.f;
        CVTACC(u000, ka.x);
        CVTACC(u001, ka.y);
        CVTACC(u010, ka.z);
        CVTACC(u011, ka.w);
        CVTACC(u100, kb.x);
        CVTACC(u101, kb.y);
        CVTACC(u110, kb.z);
        CVTACC(u111, kb.w);

        // packed bf16 hi/lo split (mask already folded into weights)
        const __nv_bfloat162 h01 = __floats2bfloat162_rn(v0, v1);
        const __nv_bfloat162 h23 = __floats2bfloat162_rn(v2, v3);
        const float2 f01 = __bfloat1622float2(h01);
        const float2 f23 = __bfloat1622float2(h23);
        const __nv_bfloat162 l01 = __floats2bfloat162_rn(v0 - f01.x, v1 - f01.y);
        const __nv_bfloat162 l23 = __floats2bfloat162_rn(v2 - f23.x, v3 - f23.y);

        uint2 shi, slo;
        shi.x = *(const uint32_t*)&h01; shi.y = *(const uint32_t*)&h23;
        slo.x = *(const uint32_t*)&l01; slo.y = *(const uint32_t*)&l23;

        // SW128-swizzled STS.64: row = p (128B), cols = 4 channels (8B)
        const uint32_t off = (uint32_t)(p * 128 + lane16 * 8);
        const uint32_t sw  = off ^ (uint32_t)((p & 7) << 4);
        *(uint2*)(smem + abase + sw)        = shi;
        *(uint2*)(smem + abase + A_LO + sw) = slo;
    }
}

// ---------------------------------------------------------------------------
// Fused deformable conv3d, software-pipelined:
//   iteration k: gather(tap k+1 -> A buf (k+1)&1) | GEMM(tap k from buf k&1)
//   single __syncthreads per iteration.
// ---------------------------------------------------------------------------
__global__ __launch_bounds__(256, 2)
void deform_conv3d_kernel(const float* __restrict__ offset,
                          const float* __restrict__ mask,
                          float* __restrict__ out) {
    extern __shared__ char smem[];
    const uint32_t sb = s2u(smem);

    const int t      = threadIdx.x;
    const int lane   = t & 31;
    const int warp   = t >> 5;
    const int lane16 = lane & 15;
    const int sub    = lane >> 4;
    const int pbase  = blockIdx.x * P_TILE;
    const int pw     = warp * 16;

    // GEMM warp tile: 4(p) x 2(co) warp grid, 32p x 32co per warp
    const int pblk = (warp & 3) * 32;
    const int cblk = (warp >> 2) * 32;

    const int lrr = lane & 7;
    const int a_row_off = lrr + ((lane >> 3) & 1) * 8;
    const int a_colh    = (lane >> 4) & 1;
    const int b_row_off = lrr + ((lane >> 4) & 1) * 8;
    const int b_colh    = (lane >> 3) & 1;

    const uint32_t a_sx[2] = { (uint32_t)(((pblk + 0 * 16 + a_row_off) & 7) << 4),
                               (uint32_t)(((pblk + 1 * 16 + a_row_off) & 7) << 4) };
    const uint32_t b_sx[2] = { (uint32_t)(((cblk + 0 * 16 + b_row_off) & 7) << 4),
                               (uint32_t)(((cblk + 1 * 16 + b_row_off) & 7) << 4) };
    const uint32_t a_rb[2] = { (uint32_t)((pblk + 0 * 16 + a_row_off) * 128),
                               (uint32_t)((pblk + 1 * 16 + a_row_off) * 128) };
    const uint32_t b_rb[2] = { (uint32_t)((cblk + 0 * 16 + b_row_off) * 128),
                               (uint32_t)((cblk + 1 * 16 + b_row_off) * 128) };

    float acc[2][4][4];
#pragma unroll
    for (int i = 0; i < 2; ++i)
#pragma unroll
        for (int j = 0; j < 4; ++j)
#pragma unroll
            for (int q = 0; q < 4; ++q) acc[i][j][q] = 0.f;

    // prologue: weights tap 0 + gather tap 0 into buffer 0
    stage_w(sb + OFF_W, 0, t);
    gather_tap(smem, OFF_A, 0, offset, mask, pw, sub, lane16, pbase);
    __syncthreads();

    for (int k = 0; k < KPROD; ++k) {
        if (k < KPROD - 1) {
            stage_w(sb + OFF_W + (uint32_t)((k + 1) & 1) * 16384, k + 1, t);
            gather_tap(smem, OFF_A + (uint32_t)((k + 1) & 1) * A_BUF_SZ, k + 1,
                       offset, mask, pw, sub, lane16, pbase);
        }

        if (k == KPROD - 1)
            asm volatile("cp.async.wait_group 0;" ::: "memory");
        else
            asm volatile("cp.async.wait_group 1;" ::: "memory");

        // ---- GEMM: tap k ----
        const uint32_t wS  = sb + OFF_W + (uint32_t)(k & 1) * 16384;
        const uint32_t a0b = sb + OFF_A + (uint32_t)(k & 1) * A_BUF_SZ;
        const uint32_t a1b = a0b + A_LO;
#pragma unroll
        for (int ks = 0; ks < 4; ++ks) {
            const uint32_t cbA = ((uint32_t)(ks * 32 + a_colh * 16));
            const uint32_t cbB = ((uint32_t)(ks * 32 + b_colh * 16));
            uint32_t A0[2][4], A1[2][4], B0[2][4], B1[2][4];
#pragma unroll
            for (int pt = 0; pt < 2; ++pt) {
                const uint32_t ad = a_rb[pt] + (cbA ^ a_sx[pt]);
                ldmx4(A0[pt], a0b + ad);
                ldmx4(A1[pt], a1b + ad);
            }
#pragma unroll
            for (int b2 = 0; b2 < 2; ++b2) {
                const uint32_t bd = b_rb[b2] + (cbB ^ b_sx[b2]);
                ldmx4(B0[b2], wS + bd);
                ldmx4(B1[b2], wS + 8192 + bd);
            }
#pragma unroll
            for (int pt = 0; pt < 2; ++pt)
#pragma unroll
                for (int bt = 0; bt < 4; ++bt) {
                    const int b2 = bt >> 1, hh = (bt & 1) * 2;
                    mma16816(acc[pt][bt], A0[pt], B0[b2][hh], B0[b2][hh + 1]);
                    mma16816(acc[pt][bt], A0[pt], B1[b2][hh], B1[b2][hh + 1]);
                    mma16816(acc[pt][bt], A1[pt], B0[b2][hh], B0[b2][hh + 1]);
                }
        }
        __syncthreads();
    }

    // ---- epilogue: D frag layout -> out[co][p] ----
    const int prow = lane >> 2;
    const int pcol = (lane & 3) * 2;
#pragma unroll
    for (int pt = 0; pt < 2; ++pt)
#pragma unroll
        for (int bt = 0; bt < 4; ++bt) {
            const int p0 = pbase + pblk + pt * 16 + prow;
            const int co = cblk + bt * 8 + pcol;
            out[(size_t)co * HWL + p0]           = acc[pt][bt][0];
            out[(size_t)(co + 1) * HWL + p0]     = acc[pt][bt][1];
            out[(size_t)co * HWL + p0 + 8]       = acc[pt][bt][2];
            out[(size_t)(co + 1) * HWL + p0 + 8] = acc[pt][bt][3];
        }
}

// ---------------------------------------------------------------------------
extern "C" void kernel_launch(void* const* d_in, const int* in_sizes, int n_in,
                              void* d_out, int out_size) {
    const float* x = nullptr;
    const float* offset = nullptr;
    const float* mask = nullptr;
    const float* weight = nullptr;
    for (int i = 0; i < n_in; ++i) {
        switch (in_sizes[i]) {
            case 2097152: x      = (const float*)d_in[i]; break;  // [1,64,32,32,32]
            case 2654208: offset = (const float*)d_in[i]; break;  // [1,81,32,32,32]
            case 884736:  mask   = (const float*)d_in[i]; break;  // [1,27,32,32,32]
            case 110592:  weight = (const float*)d_in[i]; break;  // [64,64,3,3,3]
        }
    }

    static bool s_attr_done = false;
    if (!s_attr_done) {
        cudaFuncSetAttribute(deform_conv3d_kernel,
                             cudaFuncAttributeMaxDynamicSharedMemorySize, SMEM_BYTES);
        s_attr_done = true;
    }

    prep_kernel<<<2480, 256>>>(x, weight);
    deform_conv3d_kernel<<<HWL / P_TILE, 256, SMEM_BYTES>>>(offset, mask, (float*)d_out);
}

// round 14
// speedup vs baseline: 1.7318x; 1.3183x over previous
#include <cuda_runtime.h>
#include <cuda_fp16.h>
#include <cstdint>

#define HWL    32768          // 32*32*32 spatial positions
#define CDIM   64             // in channels == out channels
#define KPROD  27             // 3*3*3 taps
#define P_TILE 128            // output positions per CTA (= GEMM M)

// Padded channels-last x in fp16: guard bands let the gather skip ALL bounds
// checks (validity folded into weights; pads are zero — harmless reads).
#define PAD_LO 560000
#define PAD_HI 700000
__device__ __align__(16) __half g_xhp[PAD_LO + HWL * CDIM + PAD_HI];
__device__ __align__(16) unsigned char g_wb[KPROD * 8192];
// per tap: 8KB fp16; rows = cout (128B each, 64 c x fp16), SW128-swizzled

__device__ __forceinline__ uint32_t s2u(const void* p) {
    uint32_t a;
    asm("{ .reg .u64 t; cvta.to.shared.u64 t, %1; cvt.u32.u64 %0, t; }"
        : "=r"(a) : "l"(p));
    return a;
}

__device__ __forceinline__ void ldmx4(uint32_t* r, uint32_t addr) {
    asm volatile("ldmatrix.sync.aligned.m8n8.x4.shared.b16 {%0,%1,%2,%3}, [%4];"
                 : "=r"(r[0]), "=r"(r[1]), "=r"(r[2]), "=r"(r[3]) : "r"(addr));
}

__device__ __forceinline__ void mma16816f16(float* d, const uint32_t* a,
                                            uint32_t b0, uint32_t b1) {
    asm volatile(
        "mma.sync.aligned.m16n8k16.row.col.f32.f16.f16.f32 "
        "{%0,%1,%2,%3}, {%4,%5,%6,%7}, {%8,%9}, {%0,%1,%2,%3};"
        : "+f"(d[0]), "+f"(d[1]), "+f"(d[2]), "+f"(d[3])
        : "r"(a[0]), "r"(a[1]), "r"(a[2]), "r"(a[3]), "r"(b0), "r"(b1));
}

// smem layout (bytes from dynamic smem base)
#define OFF_A      0
#define A_BUF_SZ   16384                     // 128 rows x 128B fp16, SW128
#define OFF_W      32768                     // weight stages: 2 x 8KB
#define OFF_META   (OFF_W + 16384)           // per-position metadata: 128 x 48B
#define SMEM_BYTES (OFF_META + 128 * 48)     // 55296 -> 2 CTAs/SM (regs-capped)

// ---------------------------------------------------------------------------
// Fused prep: blocks [0,2048) transpose x -> g_xhp[PAD_LO + s*64 + c] (fp16);
//             blocks [2048,2480) weight -> fp16, pre-swizzled [k][co][c]
// ---------------------------------------------------------------------------
__global__ __launch_bounds__(256) void prep_kernel(const float* __restrict__ x,
                                                   const float* __restrict__ w) {
    const int b = blockIdx.x;
    if (b < 2048) {
        __shared__ float tile[32][33];
        const int sbase = (b & 1023) * 32;
        const int cbase = (b >> 10) * 32;
        const int tx = threadIdx.x & 31, ty = threadIdx.x >> 5;
#pragma unroll
        for (int i = 0; i < 4; ++i) {
            const int c = ty + i * 8;
            tile[c][tx] = x[(cbase + c) * HWL + sbase + tx];
        }
        __syncthreads();
#pragma unroll
        for (int i = 0; i < 4; ++i) {
            const int s = ty + i * 8;
            g_xhp[PAD_LO + (sbase + s) * CDIM + cbase + tx] =
                __float2half_rn(tile[tx][s]);
        }
    } else {
        const int tid = (b - 2048) * 256 + threadIdx.x;   // < 27*4096 exactly
        const int k   = tid >> 12;
        const int rem = tid & 4095;
        const int co  = rem >> 6;
        const int c   = rem & 63;
        const float v = w[(co * CDIM + c) * KPROD + k];
        const uint32_t off = co * 128 + c * 2;            // row=co, 128B/row
        const uint32_t sw  = off ^ ((off >> 3) & 0x70);   // SW128
        *(__half*)(g_wb + k * 8192 + sw) = __float2half_rn(v);
    }
}

// stage one tap's 8KB fp16 weight slab via cp.async (identity copy)
__device__ __forceinline__ void stage_w(uint32_t dst, int k, int t) {
    const char* src = (const char*)g_wb + k * 8192 + t * 16;
    const uint32_t d = dst + t * 16;
#pragma unroll
    for (int i = 0; i < 2; ++i)
        asm volatile("cp.async.cg.shared.global [%0], [%1], 16;"
                     :: "r"(d + i * 4096), "l"(src + i * 4096) : "memory");
    asm volatile("cp.async.commit_group;");
}

// convert one corner (4 fp16 channels) and accumulate with weight kw
#define CVTACC(u, kw)                                                        \
    do { const float2 _a = __half22float2(*(const __half2*)&(u).x);          \
         const float2 _b = __half22float2(*(const __half2*)&(u).y);          \
         const float _k = (kw);                                              \
         v0 += _k * _a.x; v1 += _k * _a.y;                                   \
         v2 += _k * _b.x; v3 += _k * _b.y; } while (0)

// ---------------------------------------------------------------------------
// Gather one tap into an A buffer (fp16, SW128 rows = position).
//   Phase M (once per tap per warp): per-position metadata — 8 corner
//     weights (mask folded) + base index — to warp-private smem; __syncwarp.
//   Phase G (8 passes x 2 positions): broadcast-LDS metadata, 8 constant-
//     offset fp16 corner loads (128B contiguous each), interp in fp32,
//     round to fp16, single swizzled STS.64.
// ---------------------------------------------------------------------------
__device__ __forceinline__ void gather_tap(
    char* smem, uint32_t abase, int k,
    const float* __restrict__ offset, const float* __restrict__ mask,
    int pw, int sub, int lane16, int pbase)
{
    const int ki = k / 9;
    const int kj = (k % 9) / 3;
    const int kk = k % 3;

    // ---- Phase M: metadata for this warp's 16 positions ----
    {
        const int mp  = pw + lane16;          // position in tile
        const int pgm = pbase + mp;           // global position
        const int pl  = pgm & 31;
        const int pwo = (pgm >> 5) & 31;
        const int pho = pgm >> 10;

        const float och = offset[(k * 3 + 0) * HWL + pgm];
        const float ocw = offset[(k * 3 + 1) * HWL + pgm];
        const float ocl = offset[(k * 3 + 2) * HWL + pgm];
        const float m   = mask[k * HWL + pgm];

        const float ch = och + (float)(pho - 1 + ki);
        const float cw = ocw + (float)(pwo - 1 + kj);
        const float cl = ocl + (float)(pl - 1 + kk);

        const float hf = floorf(ch), wf = floorf(cw), lf = floorf(cl);
        int h0 = (int)hf, w0 = (int)wf, l0 = (int)lf;
        const float fh = ch - hf, fw = cw - wf, fl = cl - lf;

        const float wh0 = ((unsigned)h0 < 32u)       ? 1.f - fh : 0.f;
        const float wh1 = ((unsigned)(h0 + 1) < 32u) ? fh       : 0.f;
        const float ww0 = ((unsigned)w0 < 32u)       ? 1.f - fw : 0.f;
        const float ww1 = ((unsigned)(w0 + 1) < 32u) ? fw       : 0.f;
        const float wl0 = ((unsigned)l0 < 32u)       ? 1.f - fl : 0.f;
        const float wl1 = ((unsigned)(l0 + 1) < 32u) ? fl       : 0.f;

        h0 = max(-8, min(h0, 40));
        w0 = max(-8, min(w0, 40));
        l0 = max(-8, min(l0, 40));
        const int base = PAD_LO + ((h0 * 32 + w0) * 32 + l0) * CDIM;

        const float w00 = wh0 * ww0 * m, w01 = wh0 * ww1 * m;
        const float w10 = wh1 * ww0 * m, w11 = wh1 * ww1 * m;

        if (lane16 == (threadIdx.x & 31)) {   // lanes 0..15 only
            char* mrow = smem + OFF_META + mp * 48;
            *(float4*)(mrow)      = make_float4(w00 * wl0, w00 * wl1,
                                                w01 * wl0, w01 * wl1);
            *(float4*)(mrow + 16) = make_float4(w10 * wl0, w10 * wl1,
                                                w11 * wl0, w11 * wl1);
            *(int*)(mrow + 32)    = base;
        }
    }
    __syncwarp();

    // ---- Phase G: gather using metadata ----
#pragma unroll 2
    for (int iter = 0; iter < 8; ++iter) {
        const int idx = iter * 2 + sub;
        const int p   = pw + idx;

        const char* mrow = smem + OFF_META + p * 48;
        const float4 ka = *(const float4*)(mrow);
        const float4 kb = *(const float4*)(mrow + 16);
        const int  base = *(const int*)(mrow + 32);

        const __half* bp = g_xhp + base + lane16 * 4;

        // 8 corner loads (fp16): constant offsets, back-to-back, 128B each
        const uint2 u000 = *(const uint2*)(bp + 0);
        const uint2 u001 = *(const uint2*)(bp + 64);
        const uint2 u010 = *(const uint2*)(bp + 2048);
        const uint2 u011 = *(const uint2*)(bp + 2112);
        const uint2 u100 = *(const uint2*)(bp + 65536);
        const uint2 u101 = *(const uint2*)(bp + 65600);
        const uint2 u110 = *(const uint2*)(bp + 67584);
        const uint2 u111 = *(const uint2*)(bp + 67648);

        float v0 = 0.f, v1 = 0.f, v2 = 0.f, v3 = 0.f;
        CVTACC(u000, ka.x);
        CVTACC(u001, ka.y);
        CVTACC(u010, ka.z);
        CVTACC(u011, ka.w);
        CVTACC(u100, kb.x);
        CVTACC(u101, kb.y);
        CVTACC(u110, kb.z);
        CVTACC(u111, kb.w);

        // round to fp16 (mask already folded into weights)
        const __half2 p01 = __floats2half2_rn(v0, v1);
        const __half2 p23 = __floats2half2_rn(v2, v3);
        uint2 sv;
        sv.x = *(const uint32_t*)&p01;
        sv.y = *(const uint32_t*)&p23;

        // SW128-swizzled STS.64: row = p (128B), cols = 4 channels (8B)
        const uint32_t off = (uint32_t)(p * 128 + lane16 * 8);
        const uint32_t sw  = off ^ (uint32_t)((p & 7) << 4);
        *(uint2*)(smem + abase + sw) = sv;
    }
}

// ---------------------------------------------------------------------------
// Fused deformable conv3d, software-pipelined, fp16 single-term GEMM:
//   iteration k: gather(tap k+1 -> A buf (k+1)&1) | GEMM(tap k from buf k&1)
//   single __syncthreads per iteration.
// ---------------------------------------------------------------------------
__global__ __launch_bounds__(256, 2)
void deform_conv3d_kernel(const float* __restrict__ offset,
                          const float* __restrict__ mask,
                          float* __restrict__ out) {
    extern __shared__ char smem[];
    const uint32_t sb = s2u(smem);

    const int t      = threadIdx.x;
    const int lane   = t & 31;
    const int warp   = t >> 5;
    const int lane16 = lane & 15;
    const int sub    = lane >> 4;
    const int pbase  = blockIdx.x * P_TILE;
    const int pw     = warp * 16;

    // GEMM warp tile: 4(p) x 2(co) warp grid, 32p x 32co per warp
    const int pblk = (warp & 3) * 32;
    const int cblk = (warp >> 2) * 32;

    const int lrr = lane & 7;
    const int a_row_off = lrr + ((lane >> 3) & 1) * 8;
    const int a_colh    = (lane >> 4) & 1;
    const int b_row_off = lrr + ((lane >> 4) & 1) * 8;
    const int b_colh    = (lane >> 3) & 1;

    const uint32_t a_sx[2] = { (uint32_t)(((pblk + 0 * 16 + a_row_off) & 7) << 4),
                               (uint32_t)(((pblk + 1 * 16 + a_row_off) & 7) << 4) };
    const uint32_t b_sx[2] = { (uint32_t)(((cblk + 0 * 16 + b_row_off) & 7) << 4),
                               (uint32_t)(((cblk + 1 * 16 + b_row_off) & 7) << 4) };
    const uint32_t a_rb[2] = { (uint32_t)((pblk + 0 * 16 + a_row_off) * 128),
                               (uint32_t)((pblk + 1 * 16 + a_row_off) * 128) };
    const uint32_t b_rb[2] = { (uint32_t)((cblk + 0 * 16 + b_row_off) * 128),
                               (uint32_t)((cblk + 1 * 16 + b_row_off) * 128) };

    float acc[2][4][4];
#pragma unroll
    for (int i = 0; i < 2; ++i)
#pragma unroll
        for (int j = 0; j < 4; ++j)
#pragma unroll
            for (int q = 0; q < 4; ++q) acc[i][j][q] = 0.f;

    // prologue: weights tap 0 + gather tap 0 into buffer 0
    stage_w(sb + OFF_W, 0, t);
    gather_tap(smem, OFF_A, 0, offset, mask, pw, sub, lane16, pbase);
    __syncthreads();

    for (int k = 0; k < KPROD; ++k) {
        if (k < KPROD - 1) {
            stage_w(sb + OFF_W + (uint32_t)((k + 1) & 1) * 8192, k + 1, t);
            gather_tap(smem, OFF_A + (uint32_t)((k + 1) & 1) * A_BUF_SZ, k + 1,
                       offset, mask, pw, sub, lane16, pbase);
        }

        if (k == KPROD - 1)
            asm volatile("cp.async.wait_group 0;" ::: "memory");
        else
            asm volatile("cp.async.wait_group 1;" ::: "memory");

        // ---- GEMM: tap k (fp16 single-term) ----
        const uint32_t wS  = sb + OFF_W + (uint32_t)(k & 1) * 8192;
        const uint32_t a0b = sb + OFF_A + (uint32_t)(k & 1) * A_BUF_SZ;
#pragma unroll
        for (int ks = 0; ks < 4; ++ks) {
            const uint32_t cbA = ((uint32_t)(ks * 32 + a_colh * 16));
            const uint32_t cbB = ((uint32_t)(ks * 32 + b_colh * 16));
            uint32_t A0[2][4], B0[2][4];
#pragma unroll
            for (int pt = 0; pt < 2; ++pt)
                ldmx4(A0[pt], a0b + a_rb[pt] + (cbA ^ a_sx[pt]));
#pragma unroll
            for (int b2 = 0; b2 < 2; ++b2)
                ldmx4(B0[b2], wS + b_rb[b2] + (cbB ^ b_sx[b2]));
#pragma unroll
            for (int pt = 0; pt < 2; ++pt)
#pragma unroll
                for (int bt = 0; bt < 4; ++bt) {
                    const int b2 = bt >> 1, hh = (bt & 1) * 2;
                    mma16816f16(acc[pt][bt], A0[pt], B0[b2][hh], B0[b2][hh + 1]);
                }
        }
        __syncthreads();
    }

    // ---- epilogue: D frag layout -> out[co][p] ----
    const int prow = lane >> 2;
    const int pcol = (lane & 3) * 2;
#pragma unroll
    for (int pt = 0; pt < 2; ++pt)
#pragma unroll
        for (int bt = 0; bt < 4; ++bt) {
            const int p0 = pbase + pblk + pt * 16 + prow;
            const int co = cblk + bt * 8 + pcol;
            out[(size_t)co * HWL + p0]           = acc[pt][bt][0];
            out[(size_t)(co + 1) * HWL + p0]     = acc[pt][bt][1];
            out[(size_t)co * HWL + p0 + 8]       = acc[pt][bt][2];
            out[(size_t)(co + 1) * HWL + p0 + 8] = acc[pt][bt][3];
        }
}

// ---------------------------------------------------------------------------
extern "C" void kernel_launch(void* const* d_in, const int* in_sizes, int n_in,
                              void* d_out, int out_size) {
    const float* x = nullptr;
    const float* offset = nullptr;
    const float* mask = nullptr;
    const float* weight = nullptr;
    for (int i = 0; i < n_in; ++i) {
        switch (in_sizes[i]) {
            case 2097152: x      = (const float*)d_in[i]; break;  // [1,64,32,32,32]
            case 2654208: offset = (const float*)d_in[i]; break;  // [1,81,32,32,32]
            case 884736:  mask   = (const float*)d_in[i]; break;  // [1,27,32,32,32]
            case 110592:  weight = (const float*)d_in[i]; break;  // [64,64,3,3,3]
        }
    }

    static bool s_attr_done = false;
    if (!s_attr_done) {
        cudaFuncSetAttribute(deform_conv3d_kernel,
                             cudaFuncAttributeMaxDynamicSharedMemorySize, SMEM_BYTES);
        s_attr_done = true;
    }

    prep_kernel<<<2480, 256>>>(x, weight);
    deform_conv3d_kernel<<<HWL / P_TILE, 256, SMEM_BYTES>>>(offset, mask, (float*)d_out);
}